// round 15
// baseline (speedup 1.0000x reference)
#include <cuda_runtime.h>
#include <math.h>
#include <float.h>

#define GRID  296      // 2 CTAs per SM x 148 SMs
#define NT    256
#define CELLB 256      // blocks [0,CELLB) do LSTM cells; [CELLB,GRID) do MLP
#define Bn 64
#define Tn 2048
#define Ln 200
#define Hn 256
#define Vn 33

// ---------------- persistent device state ----------------
__device__ float gW0[1024 * 768];          // cell0 rows: [w_ih0_row(512) | w_hh0_row(256)]
__device__ float gW12[2 * 1024 * 512];     // cells 1,2 rows: [w_ih(256) | w_hh(256)]
__device__ float gBias[3 * 1024];          // b_ih + b_hh per layer
__device__ float g_h[2][3][Bn][Hn];        // double-buffered hidden states
__device__ float g_c[3][Bn][Hn];           // cell states (elementwise in-place safe)
__device__ float g_ctxU[2][Bn][Hn];        // UNnormalized context, double-buffered
__device__ float g_denom[2][Bn];           // softmax denominator, double-buffered
__device__ unsigned g_bar;                 // grid barrier counter

struct __align__(16) SM {
    union {
        struct { float xs[4][768]; float gsm[256]; } cell;   // 13.3 KB
        struct { float4 cs[8][64]; float rs[8]; } ctx;       // 8.2 KB
        struct { float zs[2][512]; float hs[2][512]; } mlp;  // 8 KB
    } u;
};

// ---------------- helpers ----------------
__device__ __forceinline__ float sigm(float x) { return 1.0f / (1.0f + __expf(-x)); }
__device__ __forceinline__ float tanhx(float x) {
    float e = __expf(-2.0f * fabsf(x));
    float r = (1.0f - e) / (1.0f + e);
    return x < 0.0f ? -r : r;
}
__device__ __forceinline__ float dot4(float4 a, float4 b) {
    return fmaf(a.x, b.x, fmaf(a.y, b.y, fmaf(a.z, b.z, a.w * b.w)));
}

// grid-wide barrier: monotonic counter (reset by prep each launch)
__device__ __forceinline__ void gsync(unsigned &expect) {
    __syncthreads();
    if (threadIdx.x == 0) {
        expect += GRID;
        __threadfence();
        atomicAdd(&g_bar, 1u);
        while (*((volatile unsigned *)&g_bar) < expect) { }
        __threadfence();
    }
    __syncthreads();
}

// ---------------- prep: concat weights, zero state, reset barrier ----------------
__global__ void prep_kernel(const float *__restrict__ w_ih0, const float *__restrict__ w_hh0,
                            const float *__restrict__ b_ih0, const float *__restrict__ b_hh0,
                            const float *__restrict__ w_ih_r, const float *__restrict__ w_hh_r,
                            const float *__restrict__ b_ih_r, const float *__restrict__ b_hh_r)
{
    const int ns = gridDim.x * blockDim.x;
    const int t0 = blockIdx.x * blockDim.x + threadIdx.x;
    for (int i = t0; i < 1024 * 768; i += ns) {
        int r = i / 768, k = i - r * 768;
        gW0[i] = (k < 512) ? w_ih0[r * 512 + k] : w_hh0[r * 256 + (k - 512)];
    }
    for (int i = t0; i < 2 * 1024 * 512; i += ns) {
        int li = i >> 19;
        int rem = i & ((1 << 19) - 1);
        int r = rem >> 9, k = rem & 511;
        gW12[i] = (k < 256) ? w_ih_r[((size_t)li * 1024 + r) * 256 + k]
                            : w_hh_r[((size_t)li * 1024 + r) * 256 + (k - 256)];
    }
    for (int i = t0; i < 3 * 1024; i += ns) {
        int li = i >> 10, r = i & 1023;
        gBias[i] = (li == 0) ? (b_ih0[r] + b_hh0[r])
                             : (b_ih_r[(li - 1) * 1024 + r] + b_hh_r[(li - 1) * 1024 + r]);
    }
    for (int i = t0; i < 2 * 3 * Bn * Hn; i += ns) ((float *)g_h)[i] = 0.0f;
    for (int i = t0; i < 3 * Bn * Hn; i += ns) ((float *)g_c)[i] = 0.0f;
    for (int i = t0; i < 2 * Bn * Hn; i += ns) ((float *)g_ctxU)[i] = 0.0f;
    for (int i = t0; i < 2 * Bn; i += ns) ((float *)g_denom)[i] = 1.0f;
    if (t0 == 0) g_bar = 0u;
}

// ------------- LSTM cell phase (blocks 0..255): tile 4b x 16j, 8 rows/warp -------------
template<int KC>
__device__ void cell_phase(int L, int l, int cur, int prv,
                           const float *__restrict__ W,
                           const float *__restrict__ emb, const int *__restrict__ labels, SM *s)
{
    const int blk = blockIdx.x, tid = threadIdx.x;
    const int w = tid >> 5, lane = tid & 31;
    const int b0 = (blk >> 4) * 4;     // 16 b-groups
    const int j0 = (blk & 15) * 16;    // 16 j-groups
    const float *bias = gBias + L * 1024;

    // stage xcat for 4 batches into smem
    if (L == 0) {
        for (int i = tid; i < 4 * 256; i += NT) {
            int bi = i >> 8, k = i & 255, b = b0 + bi;
            int lab = labels[l * Bn + b];
            float rd = 1.0f / g_denom[prv][b];
            s->u.cell.xs[bi][k]       = emb[(size_t)lab * 256 + k];
            s->u.cell.xs[bi][256 + k] = g_ctxU[prv][b][k] * rd;
            s->u.cell.xs[bi][512 + k] = g_h[prv][0][b][k];
        }
    } else {
        for (int i = tid; i < 4 * 256; i += NT) {
            int bi = i >> 8, k = i & 255, b = b0 + bi;
            s->u.cell.xs[bi][k]       = g_h[cur][L - 1][b][k];
            s->u.cell.xs[bi][256 + k] = g_h[prv][L][b][k];
        }
    }
    __syncthreads();

    const float4 *X0 = (const float4 *)s->u.cell.xs[0];
    const float4 *X1 = (const float4 *)s->u.cell.xs[1];
    const float4 *X2 = (const float4 *)s->u.cell.xs[2];
    const float4 *X3 = (const float4 *)s->u.cell.xs[3];
    constexpr int C = KC >> 7;   // 128-float chunks: 6 (cell0) or 4

    // 64 units = (gate g, jj<16) ; warp w handles units [8w, 8w+8)
#pragma unroll 2
    for (int i = 0; i < 8; i++) {
        int u = w * 8 + i;
        int g = u & 3, jj = u >> 2;
        int r = g * 256 + j0 + jj;
        const float4 *wr = (const float4 *)(W + (size_t)r * KC);
        float a0 = 0.f, a1 = 0.f, a2 = 0.f, a3 = 0.f;
#pragma unroll
        for (int c = 0; c < C; c++) {
            float4 wv = wr[c * 32 + lane];
            a0 += dot4(wv, X0[c * 32 + lane]);
            a1 += dot4(wv, X1[c * 32 + lane]);
            a2 += dot4(wv, X2[c * 32 + lane]);
            a3 += dot4(wv, X3[c * 32 + lane]);
        }
#pragma unroll
        for (int off = 16; off; off >>= 1) {
            a0 += __shfl_xor_sync(0xffffffffu, a0, off);
            a1 += __shfl_xor_sync(0xffffffffu, a1, off);
            a2 += __shfl_xor_sync(0xffffffffu, a2, off);
            a3 += __shfl_xor_sync(0xffffffffu, a3, off);
        }
        if (lane == 0) {
            float bb = bias[r];
            s->u.cell.gsm[(jj * 4 + g) * 4 + 0] = a0 + bb;
            s->u.cell.gsm[(jj * 4 + g) * 4 + 1] = a1 + bb;
            s->u.cell.gsm[(jj * 4 + g) * 4 + 2] = a2 + bb;
            s->u.cell.gsm[(jj * 4 + g) * 4 + 3] = a3 + bb;
        }
    }
    __syncthreads();
    if (tid < 64) {
        int jj = tid >> 2, bi = tid & 3;
        int b = b0 + bi, j = j0 + jj;
        float gi = s->u.cell.gsm[(jj * 4 + 0) * 4 + bi];
        float gf = s->u.cell.gsm[(jj * 4 + 1) * 4 + bi];
        float gg = s->u.cell.gsm[(jj * 4 + 2) * 4 + bi];
        float go = s->u.cell.gsm[(jj * 4 + 3) * 4 + bi];
        float co = g_c[L][b][j];
        float cn = sigm(gf) * co + sigm(gi) * tanhx(gg);
        g_c[L][b][j] = cn;
        g_h[cur][L][b][j] = sigm(go) * tanhx(cn);
    }
}

// ---------------- MLP head for a group of 2 batches ----------------
__device__ void mlp_g(int g, int hb, int ol,
                      const float *__restrict__ fc1w, const float *__restrict__ fc1b,
                      const float *__restrict__ fc2w, const float *__restrict__ fc2b,
                      float *__restrict__ out, SM *s)
{
    const int tid = threadIdx.x, w = tid >> 5, lane = tid & 31;
    const int b0 = g * 2;
    __syncthreads();
    for (int i = tid; i < 2 * 512; i += NT) {
        int bi = i >> 9, k = i & 511, b = b0 + bi;
        s->u.mlp.zs[bi][k] = (k < 256) ? g_h[hb][2][b][k]
                                       : g_ctxU[hb][b][k - 256] * (1.0f / g_denom[hb][b]);
    }
    __syncthreads();
    const float4 *z40 = (const float4 *)s->u.mlp.zs[0];
    const float4 *z41 = (const float4 *)s->u.mlp.zs[1];
    float4 z0[4], z1[4];
#pragma unroll
    for (int c = 0; c < 4; c++) { z0[c] = z40[c * 32 + lane]; z1[c] = z41[c * 32 + lane]; }
    // fc1: warp w handles rows [w*64, w*64+64), 2 rows at a time
    for (int r = w * 64; r < w * 64 + 64; r += 2) {
        const float4 *wr0 = (const float4 *)(fc1w + (size_t)r * 512);
        const float4 *wr1 = (const float4 *)(fc1w + (size_t)(r + 1) * 512);
        float a00 = 0.f, a01 = 0.f, a10 = 0.f, a11 = 0.f;
#pragma unroll
        for (int c = 0; c < 4; c++) {
            float4 w0 = wr0[c * 32 + lane], w1 = wr1[c * 32 + lane];
            a00 += dot4(w0, z0[c]); a01 += dot4(w0, z1[c]);
            a10 += dot4(w1, z0[c]); a11 += dot4(w1, z1[c]);
        }
#pragma unroll
        for (int off = 16; off; off >>= 1) {
            a00 += __shfl_xor_sync(0xffffffffu, a00, off);
            a01 += __shfl_xor_sync(0xffffffffu, a01, off);
            a10 += __shfl_xor_sync(0xffffffffu, a10, off);
            a11 += __shfl_xor_sync(0xffffffffu, a11, off);
        }
        if (lane == 0) {
            float bb0 = fc1b[r], bb1 = fc1b[r + 1];
            s->u.mlp.hs[0][r]     = fmaxf(a00 + bb0, 0.0f);
            s->u.mlp.hs[1][r]     = fmaxf(a01 + bb0, 0.0f);
            s->u.mlp.hs[0][r + 1] = fmaxf(a10 + bb1, 0.0f);
            s->u.mlp.hs[1][r + 1] = fmaxf(a11 + bb1, 0.0f);
        }
    }
    __syncthreads();
    const float4 *h40 = (const float4 *)s->u.mlp.hs[0];
    const float4 *h41 = (const float4 *)s->u.mlp.hs[1];
    float4 h0[4], h1[4];
#pragma unroll
    for (int c = 0; c < 4; c++) { h0[c] = h40[c * 32 + lane]; h1[c] = h41[c * 32 + lane]; }
    for (int r = w; r < Vn; r += 8) {
        const float4 *wr = (const float4 *)(fc2w + (size_t)r * 512);
        float a0 = 0.f, a1 = 0.f;
#pragma unroll
        for (int c = 0; c < 4; c++) {
            float4 wv = wr[c * 32 + lane];
            a0 += dot4(wv, h0[c]); a1 += dot4(wv, h1[c]);
        }
#pragma unroll
        for (int off = 16; off; off >>= 1) {
            a0 += __shfl_xor_sync(0xffffffffu, a0, off);
            a1 += __shfl_xor_sync(0xffffffffu, a1, off);
        }
        if (lane == 0) {
            float bb = fc2b[r];
            out[((size_t)b0 * Ln + ol) * Vn + r]       = a0 + bb;
            out[((size_t)(b0 + 1) * Ln + ol) * Vn + r] = a1 + bb;
        }
    }
}

// ------- fused attention: p=exp(e); ctxU[cur] += p*value; denom[cur] += p -------
__device__ void attn_phase(int cur, const float *__restrict__ key,
                           const float *__restrict__ value,
                           const int *__restrict__ lens, SM *s)
{
    const int blk = blockIdx.x, tid = threadIdx.x;
    const int w = tid >> 5, lane = tid & 31;
    for (int it = blk; it < Bn * 16; it += GRID) {
        int b = it >> 4;
        int t0 = (it & 15) << 7;
        int len = lens[b];
        if (t0 >= len) continue;
        int t1 = min(t0 + 128, len);
        const float4 *q4 = (const float4 *)g_h[cur][2][b];
        float4 q0 = q4[lane], q1 = q4[lane + 32];
        float4 a0 = make_float4(0.f, 0.f, 0.f, 0.f);
        float4 a1 = make_float4(0.f, 0.f, 0.f, 0.f);
        float dp = 0.0f;
        int tw0 = t0 + w * 16;
        int tw1 = min(tw0 + 16, t1);
        for (int t = tw0; t < tw1; t += 2) {
            int n = min(2, tw1 - t);
            float4 k0[2], k1[2], v0[2], v1[2];
#pragma unroll
            for (int i = 0; i < 2; i++) {
                if (i < n) {
                    const float4 *kr = (const float4 *)(key + ((size_t)b * Tn + (t + i)) * Hn);
                    const float4 *vr = (const float4 *)(value + ((size_t)b * Tn + (t + i)) * Hn);
                    k0[i] = kr[lane]; k1[i] = kr[lane + 32];
                    v0[i] = vr[lane]; v1[i] = vr[lane + 32];
                }
            }
            float sv[2];
#pragma unroll
            for (int i = 0; i < 2; i++)
                sv[i] = (i < n) ? (dot4(k0[i], q0) + dot4(k1[i], q1)) : -1e30f;
#pragma unroll
            for (int off = 16; off; off >>= 1) {
#pragma unroll
                for (int i = 0; i < 2; i++)
                    sv[i] += __shfl_xor_sync(0xffffffffu, sv[i], off);
            }
            float p[2];
#pragma unroll
            for (int i = 0; i < 2; i++)
                p[i] = __expf(fminf(sv[i], 75.0f));   // sv=-4e30 -> 0
#pragma unroll
            for (int i = 0; i < 2; i++) {
                if (i < n) {
                    a0.x = fmaf(p[i], v0[i].x, a0.x); a0.y = fmaf(p[i], v0[i].y, a0.y);
                    a0.z = fmaf(p[i], v0[i].z, a0.z); a0.w = fmaf(p[i], v0[i].w, a0.w);
                    a1.x = fmaf(p[i], v1[i].x, a1.x); a1.y = fmaf(p[i], v1[i].y, a1.y);
                    a1.z = fmaf(p[i], v1[i].z, a1.z); a1.w = fmaf(p[i], v1[i].w, a1.w);
                    dp += p[i];
                }
            }
        }
        __syncthreads();
        s->u.ctx.cs[w][lane] = a0;
        s->u.ctx.cs[w][lane + 32] = a1;
        if (lane == 0) s->u.ctx.rs[w] = dp;   // dp already warp-total (replicated)
        __syncthreads();
        if (tid < 64) {
            float4 sum = s->u.ctx.cs[0][tid];
#pragma unroll
            for (int i = 1; i < 8; i++) {
                float4 v = s->u.ctx.cs[i][tid];
                sum.x += v.x; sum.y += v.y; sum.z += v.z; sum.w += v.w;
            }
            atomicAdd(&g_ctxU[cur][b][4 * tid + 0], sum.x);
            atomicAdd(&g_ctxU[cur][b][4 * tid + 1], sum.y);
            atomicAdd(&g_ctxU[cur][b][4 * tid + 2], sum.z);
            atomicAdd(&g_ctxU[cur][b][4 * tid + 3], sum.w);
        } else if (tid == 64) {
            float d = 0.0f;
#pragma unroll
            for (int i = 0; i < 8; i++) d += s->u.ctx.rs[i];
            atomicAdd(&g_denom[cur][b], d);
        }
    }
}

// ---------------- main persistent kernel ----------------
__global__ __launch_bounds__(NT, 2) void decoder_kernel(
    const float *__restrict__ key, const float *__restrict__ value,
    const int *__restrict__ labels, const int *__restrict__ lens,
    const float *__restrict__ emb,
    const float *__restrict__ fc1w, const float *__restrict__ fc1b,
    const float *__restrict__ fc2w, const float *__restrict__ fc2b,
    float *__restrict__ out)
{
    __shared__ SM s;
    const int blk = blockIdx.x, tid = threadIdx.x;
    unsigned expect = 0;

    for (int l = 0; l < Ln; l++) {
        const int cur = l & 1, prv = cur ^ 1;
        // ---- slot 1: zero ctxU[cur]/denom[cur]; cell0 | MLP groups [0,11) ----
        {
            int i = blk * NT + tid;
            if (i < Bn * Hn) ((float *)g_ctxU[cur])[i] = 0.0f;
            if (blk == GRID - 1 && tid < Bn) g_denom[cur][tid] = 0.0f;
        }
        if (blk < CELLB) {
            cell_phase<768>(0, l, cur, prv, gW0, emb, labels, &s);
        } else if (l > 0) {
            int m = blk - CELLB;
            if (m < 11) mlp_g(m, prv, l - 1, fc1w, fc1b, fc2w, fc2b, out, &s);
        }
        gsync(expect);
        // ---- slot 2: cell1 | MLP groups [11,22) ----
        if (blk < CELLB) {
            cell_phase<512>(1, l, cur, prv, gW12, emb, labels, &s);
        } else if (l > 0) {
            int m = blk - CELLB;
            if (m < 11) mlp_g(11 + m, prv, l - 1, fc1w, fc1b, fc2w, fc2b, out, &s);
        }
        gsync(expect);
        // ---- slot 3: cell2 | MLP groups [22,32) ----
        if (blk < CELLB) {
            cell_phase<512>(2, l, cur, prv, gW12 + (size_t)1024 * 512, emb, labels, &s);
        } else if (l > 0) {
            int m = blk - CELLB;
            if (m < 10) mlp_g(22 + m, prv, l - 1, fc1w, fc1b, fc2w, fc2b, out, &s);
        }
        gsync(expect);
        // ---- slot 4: fused attention ----
        attn_phase(cur, key, value, lens, &s);
        gsync(expect);
    }
    // final MLP for l = Ln-1 (buffer parity of 199 = 1)
    for (int g = blk; g < 32; g += GRID)
        mlp_g(g, 1, Ln - 1, fc1w, fc1b, fc2w, fc2b, out, &s);
}

// ---------------- launch ----------------
extern "C" void kernel_launch(void *const *d_in, const int *in_sizes, int n_in,
                              void *d_out, int out_size)
{
    const float *key    = (const float *)d_in[0];
    const float *value  = (const float *)d_in[1];
    const int   *labels = (const int *)d_in[2];
    const int   *lens   = (const int *)d_in[3];
    const float *emb    = (const float *)d_in[4];
    const float *w_ih0  = (const float *)d_in[5];
    const float *w_hh0  = (const float *)d_in[6];
    const float *b_ih0  = (const float *)d_in[7];
    const float *b_hh0  = (const float *)d_in[8];
    const float *w_ih_r = (const float *)d_in[9];
    const float *w_hh_r = (const float *)d_in[10];
    const float *b_ih_r = (const float *)d_in[11];
    const float *b_hh_r = (const float *)d_in[12];
    const float *fc1w   = (const float *)d_in[13];
    const float *fc1b   = (const float *)d_in[14];
    const float *fc2w   = (const float *)d_in[15];
    const float *fc2b   = (const float *)d_in[16];
    float *out = (float *)d_out;

    prep_kernel<<<592, 256>>>(w_ih0, w_hh0, b_ih0, b_hh0,
                              w_ih_r, w_hh_r, b_ih_r, b_hh_r);
    decoder_kernel<<<GRID, NT>>>(key, value, labels, lens, emb,
                                 fc1w, fc1b, fc2w, fc2b, out);
}

// round 17
// speedup vs baseline: 1.1411x; 1.1411x over previous
#include <cuda_runtime.h>
#include <math.h>
#include <float.h>

#define GRID   288
#define CELLNB 256     // blocks [0,256): cells + attention; [256,288): MLP
#define NT     256
#define Bn 64
#define Tn 2048
#define Ln 200
#define Hn 256
#define Vn 33

// ---------------- persistent device state ----------------
__device__ float gW0[1024 * 768];          // cell0 rows: [w_ih0_row(512) | w_hh0_row(256)]
__device__ float gW12[2 * 1024 * 512];     // cells 1,2 rows: [w_ih(256) | w_hh(256)]
__device__ float gBias[3 * 1024];          // b_ih + b_hh per layer
__device__ float g_h[2][3][Bn][Hn];        // double-buffered hidden states
__device__ float g_c[3][Bn][Hn];           // cell states (same-block in-place)
__device__ float g_part[2][Bn][16][260];   // attn partials: [0..255]=ctx, [256]=denom
__device__ int   g_nch[Bn];                // ceil(len/128) >= 1
// dataflow flags (monotonic counters)
__device__ unsigned fC0[16], fC1[16], fC2[16];   // per b-group, 16 arrivals / step
__device__ unsigned fCTX[Bn];                    // per b, nch arrivals / step
__device__ unsigned fMD[Bn];                     // per b, 1 arrival / step (MLP done)

struct __align__(16) SM {
    union {
        struct { float xs[4][768]; float gsm[256]; float dn[4]; } cell;
        struct { float4 cs[8][64]; float rs[8]; } ctx;
        struct { float zs[2][512]; float hs[2][512]; float dn[2]; } mlp;
    } u;
};

// ---------------- helpers ----------------
__device__ __forceinline__ float sigm(float x) { return 1.0f / (1.0f + __expf(-x)); }
__device__ __forceinline__ float tanhx(float x) {
    float e = __expf(-2.0f * fabsf(x));
    float r = (1.0f - e) / (1.0f + e);
    return x < 0.0f ? -r : r;
}
__device__ __forceinline__ float dot4(float4 a, float4 b) {
    return fmaf(a.x, b.x, fmaf(a.y, b.y, fmaf(a.z, b.z, a.w * b.w)));
}
__device__ __forceinline__ void waitf(unsigned *f, unsigned tgt) {
    volatile unsigned *vf = (volatile unsigned *)f;
    if (*vf >= tgt) return;
    while (*vf < tgt) __nanosleep(64);
}

// ---------------- prep: concat weights, zero state/flags ----------------
__global__ void prep_kernel(const float *__restrict__ w_ih0, const float *__restrict__ w_hh0,
                            const float *__restrict__ b_ih0, const float *__restrict__ b_hh0,
                            const float *__restrict__ w_ih_r, const float *__restrict__ w_hh_r,
                            const float *__restrict__ b_ih_r, const float *__restrict__ b_hh_r,
                            const int *__restrict__ lens)
{
    const int ns = gridDim.x * blockDim.x;
    const int t0 = blockIdx.x * blockDim.x + threadIdx.x;
    for (int i = t0; i < 1024 * 768; i += ns) {
        int r = i / 768, k = i - r * 768;
        gW0[i] = (k < 512) ? w_ih0[r * 512 + k] : w_hh0[r * 256 + (k - 512)];
    }
    for (int i = t0; i < 2 * 1024 * 512; i += ns) {
        int li = i >> 19;
        int rem = i & ((1 << 19) - 1);
        int r = rem >> 9, k = rem & 511;
        gW12[i] = (k < 256) ? w_ih_r[((size_t)li * 1024 + r) * 256 + k]
                            : w_hh_r[((size_t)li * 1024 + r) * 256 + (k - 256)];
    }
    for (int i = t0; i < 3 * 1024; i += ns) {
        int li = i >> 10, r = i & 1023;
        gBias[i] = (li == 0) ? (b_ih0[r] + b_hh0[r])
                             : (b_ih_r[(li - 1) * 1024 + r] + b_hh_r[(li - 1) * 1024 + r]);
    }
    for (int i = t0; i < 2 * 3 * Bn * Hn; i += ns) ((float *)g_h)[i] = 0.0f;
    for (int i = t0; i < 3 * Bn * Hn; i += ns) ((float *)g_c)[i] = 0.0f;
    for (int i = t0; i < Bn; i += ns) {
        g_nch[i] = (lens[i] + 127) >> 7;
        fCTX[i] = 0u; fMD[i] = 0u;
    }
    for (int i = t0; i < 16; i += ns) { fC0[i] = 0u; fC1[i] = 0u; fC2[i] = 0u; }
}

// ------------- LSTM cell compute: xs staged, tile 4b x 16j, 8 rows/warp -------------
template<int KC>
__device__ void cell_compute(int L, int cur, int b0, int j0,
                             const float *__restrict__ W, SM *s)
{
    const int tid = threadIdx.x;
    const int w = tid >> 5, lane = tid & 31;
    const float *bias = gBias + L * 1024;
    const float4 *X0 = (const float4 *)s->u.cell.xs[0];
    const float4 *X1 = (const float4 *)s->u.cell.xs[1];
    const float4 *X2 = (const float4 *)s->u.cell.xs[2];
    const float4 *X3 = (const float4 *)s->u.cell.xs[3];
    constexpr int C = KC >> 7;

#pragma unroll 2
    for (int i = 0; i < 8; i++) {
        int u = w * 8 + i;
        int g = u & 3, jj = u >> 2;
        int r = g * 256 + j0 + jj;
        const float4 *wr = (const float4 *)(W + (size_t)r * KC);
        float a0 = 0.f, a1 = 0.f, a2 = 0.f, a3 = 0.f;
#pragma unroll
        for (int c = 0; c < C; c++) {
            float4 wv = wr[c * 32 + lane];
            a0 += dot4(wv, X0[c * 32 + lane]);
            a1 += dot4(wv, X1[c * 32 + lane]);
            a2 += dot4(wv, X2[c * 32 + lane]);
            a3 += dot4(wv, X3[c * 32 + lane]);
        }
#pragma unroll
        for (int off = 16; off; off >>= 1) {
            a0 += __shfl_xor_sync(0xffffffffu, a0, off);
            a1 += __shfl_xor_sync(0xffffffffu, a1, off);
            a2 += __shfl_xor_sync(0xffffffffu, a2, off);
            a3 += __shfl_xor_sync(0xffffffffu, a3, off);
        }
        if (lane == 0) {
            float bb = bias[r];
            s->u.cell.gsm[(jj * 4 + g) * 4 + 0] = a0 + bb;
            s->u.cell.gsm[(jj * 4 + g) * 4 + 1] = a1 + bb;
            s->u.cell.gsm[(jj * 4 + g) * 4 + 2] = a2 + bb;
            s->u.cell.gsm[(jj * 4 + g) * 4 + 3] = a3 + bb;
        }
    }
    __syncthreads();
    if (tid < 64) {
        int jj = tid >> 2, bi = tid & 3;
        int b = b0 + bi, j = j0 + jj;
        float gi = s->u.cell.gsm[(jj * 4 + 0) * 4 + bi];
        float gf = s->u.cell.gsm[(jj * 4 + 1) * 4 + bi];
        float gg = s->u.cell.gsm[(jj * 4 + 2) * 4 + bi];
        float go = s->u.cell.gsm[(jj * 4 + 3) * 4 + bi];
        float co = g_c[L][b][j];
        float cn = sigm(gf) * co + sigm(gi) * tanhx(gg);
        g_c[L][b][j] = cn;
        g_h[cur][L][b][j] = sigm(go) * tanhx(cn);
    }
}

// ---------------- main persistent kernel (dataflow-synced) ----------------
__global__ __launch_bounds__(NT, 2) void decoder_kernel(
    const float *__restrict__ key, const float *__restrict__ value,
    const int *__restrict__ labels, const int *__restrict__ lens,
    const float *__restrict__ emb,
    const float *__restrict__ fc1w, const float *__restrict__ fc1b,
    const float *__restrict__ fc2w, const float *__restrict__ fc2b,
    float *__restrict__ out)
{
    __shared__ SM smem;
    SM *s = &smem;
    const int blk = blockIdx.x, tid = threadIdx.x;
    const int w = tid >> 5, lane = tid & 31;

    if (blk < CELLNB) {
        // ================= cell + attention block =================
        const int g = blk >> 4, j0 = (blk & 15) * 16, b0 = g * 4;
        const int ab = blk >> 2, ccb = (blk & 3) * 4;
        const int alen = lens[ab];
        int nch[4];
#pragma unroll
        for (int bi = 0; bi < 4; bi++) nch[bi] = g_nch[b0 + bi];
        const int anch = g_nch[ab];
        const int nval = max(0, min(anch - ccb, 4));

        for (int l = 0; l < Ln; l++) {
            const int cur = l & 1, pv = cur ^ 1;
            // ---- cell 0 ----
            if (tid == 0) {
                if (l > 0)
                    for (int bi = 0; bi < 4; bi++)
                        waitf(&fCTX[b0 + bi], (unsigned)(l * nch[bi]));
                if (l >= 2)
                    for (int bi = 0; bi < 4; bi++)
                        waitf(&fMD[b0 + bi], (unsigned)(l - 1));
                __threadfence();
            }
            __syncthreads();
            if (tid < 4) {
                float d = 1.0f;
                if (l > 0) {
                    d = 0.0f;
                    int nc = nch[tid];
                    for (int c = 0; c < nc; c++) d += g_part[pv][b0 + tid][c][256];
                }
                s->u.cell.dn[tid] = 1.0f / d;
            }
            __syncthreads();
            for (int i = tid; i < 1024; i += NT) {
                int bi = i >> 8, k = i & 255, b = b0 + bi;
                int lab = labels[l * Bn + b];
                float cx = 0.0f;
                if (l > 0) {
                    int nc = nch[bi];
                    for (int c = 0; c < nc; c++) cx += g_part[pv][b][c][k];
                }
                s->u.cell.xs[bi][k]       = emb[(size_t)lab * 256 + k];
                s->u.cell.xs[bi][256 + k] = cx * s->u.cell.dn[bi];
                s->u.cell.xs[bi][512 + k] = g_h[pv][0][b][k];
            }
            __syncthreads();
            cell_compute<768>(0, cur, b0, j0, gW0, s);
            __syncthreads();
            if (tid == 0) { __threadfence(); atomicAdd(&fC0[g], 1u); }
            // ---- cell 1 ----
            if (tid == 0) { waitf(&fC0[g], 16u * (l + 1)); __threadfence(); }
            __syncthreads();
            for (int i = tid; i < 1024; i += NT) {
                int bi = i >> 8, k = i & 255, b = b0 + bi;
                s->u.cell.xs[bi][k]       = g_h[cur][0][b][k];
                s->u.cell.xs[bi][256 + k] = g_h[pv][1][b][k];
            }
            __syncthreads();
            cell_compute<512>(1, cur, b0, j0, gW12, s);
            __syncthreads();
            if (tid == 0) { __threadfence(); atomicAdd(&fC1[g], 1u); }
            // ---- cell 2 ----
            if (tid == 0) { waitf(&fC1[g], 16u * (l + 1)); __threadfence(); }
            __syncthreads();
            for (int i = tid; i < 1024; i += NT) {
                int bi = i >> 8, k = i & 255, b = b0 + bi;
                s->u.cell.xs[bi][k]       = g_h[cur][1][b][k];
                s->u.cell.xs[bi][256 + k] = g_h[pv][2][b][k];
            }
            __syncthreads();
            cell_compute<512>(2, cur, b0, j0, gW12 + (size_t)1024 * 512, s);
            __syncthreads();
            if (tid == 0) { __threadfence(); atomicAdd(&fC2[g], 1u); }
            // ---- attention: 4 chunk slots of this block's single b ----
            if (nval > 0) {
                if (tid == 0) { waitf(&fC2[ab >> 2], 16u * (l + 1)); __threadfence(); }
                __syncthreads();
                const float4 *q4 = (const float4 *)g_h[cur][2][ab];
                float4 q0 = q4[lane], q1 = q4[lane + 32];
                for (int cc = ccb; cc < ccb + nval; cc++) {
                    int t0 = cc << 7, t1 = min(t0 + 128, alen);
                    float4 a0 = make_float4(0.f, 0.f, 0.f, 0.f);
                    float4 a1 = make_float4(0.f, 0.f, 0.f, 0.f);
                    float dp = 0.0f;
                    int tw0 = t0 + w * 16, tw1 = min(tw0 + 16, t1);
                    for (int t = tw0; t < tw1; t += 2) {
                        int n = min(2, tw1 - t);
                        float4 k0[2], k1[2], v0[2], v1[2];
#pragma unroll
                        for (int i = 0; i < 2; i++) {
                            if (i < n) {
                                const float4 *kr = (const float4 *)(key + ((size_t)ab * Tn + (t + i)) * Hn);
                                const float4 *vr = (const float4 *)(value + ((size_t)ab * Tn + (t + i)) * Hn);
                                k0[i] = kr[lane]; k1[i] = kr[lane + 32];
                                v0[i] = vr[lane]; v1[i] = vr[lane + 32];
                            }
                        }
                        float sv[2];
#pragma unroll
                        for (int i = 0; i < 2; i++)
                            sv[i] = (i < n) ? (dot4(k0[i], q0) + dot4(k1[i], q1)) : -1e30f;
#pragma unroll
                        for (int off = 16; off; off >>= 1) {
#pragma unroll
                            for (int i = 0; i < 2; i++)
                                sv[i] += __shfl_xor_sync(0xffffffffu, sv[i], off);
                        }
                        float p[2];
#pragma unroll
                        for (int i = 0; i < 2; i++)
                            p[i] = __expf(fminf(sv[i], 75.0f));
#pragma unroll
                        for (int i = 0; i < 2; i++) {
                            if (i < n) {
                                a0.x = fmaf(p[i], v0[i].x, a0.x); a0.y = fmaf(p[i], v0[i].y, a0.y);
                                a0.z = fmaf(p[i], v0[i].z, a0.z); a0.w = fmaf(p[i], v0[i].w, a0.w);
                                a1.x = fmaf(p[i], v1[i].x, a1.x); a1.y = fmaf(p[i], v1[i].y, a1.y);
                                a1.z = fmaf(p[i], v1[i].z, a1.z); a1.w = fmaf(p[i], v1[i].w, a1.w);
                                dp += p[i];
                            }
                        }
                    }
                    __syncthreads();
                    s->u.ctx.cs[w][lane] = a0;
                    s->u.ctx.cs[w][lane + 32] = a1;
                    if (lane == 0) s->u.ctx.rs[w] = dp;
                    __syncthreads();
                    if (tid < 64) {
                        float4 sum = s->u.ctx.cs[0][tid];
#pragma unroll
                        for (int i = 1; i < 8; i++) {
                            float4 v = s->u.ctx.cs[i][tid];
                            sum.x += v.x; sum.y += v.y; sum.z += v.z; sum.w += v.w;
                        }
                        ((float4 *)g_part[cur][ab][cc])[tid] = sum;
                    } else if (tid == 64) {
                        float d = 0.0f;
#pragma unroll
                        for (int i = 0; i < 8; i++) d += s->u.ctx.rs[i];
                        g_part[cur][ab][cc][256] = d;
                    }
                }
                __syncthreads();
                if (tid == 0) { __threadfence(); atomicAdd(&fCTX[ab], (unsigned)nval); }
            }
        }
    } else {
        // ================= MLP block: one pair of batches =================
        const int p = blk - CELLNB, b0 = 2 * p, b1 = b0 + 1;
        const int n0 = g_nch[b0], n1 = g_nch[b1];
        for (int l = 0; l < Ln; l++) {
            const int cur = l & 1;
            if (tid == 0) {
                waitf(&fCTX[b0], (unsigned)((l + 1) * n0));
                waitf(&fCTX[b1], (unsigned)((l + 1) * n1));
                __threadfence();
            }
            __syncthreads();
            if (tid < 2) {
                int b = b0 + tid, nc = tid ? n1 : n0;
                float d = 0.0f;
                for (int c = 0; c < nc; c++) d += g_part[cur][b][c][256];
                s->u.mlp.dn[tid] = 1.0f / d;
            }
            __syncthreads();
            for (int i = tid; i < 1024; i += NT) {
                int bi = i >> 9, k = i & 511, b = b0 + bi;
                float v;
                if (k < 256) v = g_h[cur][2][b][k];
                else {
                    int kk = k - 256, nc = bi ? n1 : n0;
                    float cx = 0.0f;
                    for (int c = 0; c < nc; c++) cx += g_part[cur][b][c][kk];
                    v = cx * s->u.mlp.dn[bi];
                }
                s->u.mlp.zs[bi][k] = v;
            }
            __syncthreads();
            // all reads of g_part/g_h done -> signal early
            if (tid == 0) {
                __threadfence();
                atomicAdd(&fMD[b0], 1u); atomicAdd(&fMD[b1], 1u);
            }
            const float4 *z40 = (const float4 *)s->u.mlp.zs[0];
            const float4 *z41 = (const float4 *)s->u.mlp.zs[1];
            float4 z0[4], z1[4];
#pragma unroll
            for (int c = 0; c < 4; c++) { z0[c] = z40[c * 32 + lane]; z1[c] = z41[c * 32 + lane]; }
            for (int r = w * 64; r < w * 64 + 64; r += 2) {
                const float4 *wr0 = (const float4 *)(fc1w + (size_t)r * 512);
                const float4 *wr1 = (const float4 *)(fc1w + (size_t)(r + 1) * 512);
                float a00 = 0.f, a01 = 0.f, a10 = 0.f, a11 = 0.f;
#pragma unroll
                for (int c = 0; c < 4; c++) {
                    float4 w0 = wr0[c * 32 + lane], w1 = wr1[c * 32 + lane];
                    a00 += dot4(w0, z0[c]); a01 += dot4(w0, z1[c]);
                    a10 += dot4(w1, z0[c]); a11 += dot4(w1, z1[c]);
                }
#pragma unroll
                for (int off = 16; off; off >>= 1) {
                    a00 += __shfl_xor_sync(0xffffffffu, a00, off);
                    a01 += __shfl_xor_sync(0xffffffffu, a01, off);
                    a10 += __shfl_xor_sync(0xffffffffu, a10, off);
                    a11 += __shfl_xor_sync(0xffffffffu, a11, off);
                }
                if (lane == 0) {
                    float bb0 = fc1b[r], bb1 = fc1b[r + 1];
                    s->u.mlp.hs[0][r]     = fmaxf(a00 + bb0, 0.0f);
                    s->u.mlp.hs[1][r]     = fmaxf(a01 + bb0, 0.0f);
                    s->u.mlp.hs[0][r + 1] = fmaxf(a10 + bb1, 0.0f);
                    s->u.mlp.hs[1][r + 1] = fmaxf(a11 + bb1, 0.0f);
                }
            }
            __syncthreads();
            const float4 *h40 = (const float4 *)s->u.mlp.hs[0];
            const float4 *h41 = (const float4 *)s->u.mlp.hs[1];
            float4 h0[4], h1[4];
#pragma unroll
            for (int c = 0; c < 4; c++) { h0[c] = h40[c * 32 + lane]; h1[c] = h41[c * 32 + lane]; }
            for (int r = w; r < Vn; r += 8) {
                const float4 *wr = (const float4 *)(fc2w + (size_t)r * 512);
                float a0 = 0.f, a1 = 0.f;
#pragma unroll
                for (int c = 0; c < 4; c++) {
                    float4 wv = wr[c * 32 + lane];
                    a0 += dot4(wv, h0[c]); a1 += dot4(wv, h1[c]);
                }
#pragma unroll
                for (int off = 16; off; off >>= 1) {
                    a0 += __shfl_xor_sync(0xffffffffu, a0, off);
                    a1 += __shfl_xor_sync(0xffffffffu, a1, off);
                }
                if (lane == 0) {
                    float bb = fc2b[r];
                    out[((size_t)b0 * Ln + l) * Vn + r] = a0 + bb;
                    out[((size_t)b1 * Ln + l) * Vn + r] = a1 + bb;
                }
            }
            __syncthreads();   // hs reuse next iteration
        }
    }
}

// ---------------- launch ----------------
extern "C" void kernel_launch(void *const *d_in, const int *in_sizes, int n_in,
                              void *d_out, int out_size)
{
    const float *key    = (const float *)d_in[0];
    const float *value  = (const float *)d_in[1];
    const int   *labels = (const int *)d_in[2];
    const int   *lens   = (const int *)d_in[3];
    const float *emb    = (const float *)d_in[4];
    const float *w_ih0  = (const float *)d_in[5];
    const float *w_hh0  = (const float *)d_in[6];
    const float *b_ih0  = (const float *)d_in[7];
    const float *b_hh0  = (const float *)d_in[8];
    const float *w_ih_r = (const float *)d_in[9];
    const float *w_hh_r = (const float *)d_in[10];
    const float *b_ih_r = (const float *)d_in[11];
    const float *b_hh_r = (const float *)d_in[12];
    const float *fc1w   = (const float *)d_in[13];
    const float *fc1b   = (const float *)d_in[14];
    const float *fc2w   = (const float *)d_in[15];
    const float *fc2b   = (const float *)d_in[16];
    float *out = (float *)d_out;

    prep_kernel<<<592, 256>>>(w_ih0, w_hh0, b_ih0, b_hh0,
                              w_ih_r, w_hh_r, b_ih_r, b_hh_r, lens);
    decoder_kernel<<<GRID, NT>>>(key, value, labels, lens, emb,
                                 fc1w, fc1b, fc2w, fc2b, out);
}